// round 5
// baseline (speedup 1.0000x reference)
#include <cuda_runtime.h>

typedef unsigned long long ull;

#define WIDTH     16384
#define WOUT      16353      // WIDTH - 32 + 1
#define NROWS     1024       // B*H = 16*64
#define FILTER_L  32
#define LUT_N     4096
#define LUT_SCALE 256.0f     // entries per unit of |x|; covers mag in [0,16)
#define TILE      2048
#define THREADS   512
#define RPT       4          // outputs per thread (TILE/THREADS)
#define SG_N      2080       // TILE + 31 halo, rounded to multiple of 16
#define NGROUPS   (SG_N/4)   // 520 float4-groups
#define OUT_SCALE 0.17782794100389226f  // sqrt(10^(-15/10))

__device__   float2 d_lut[LUT_N];
__device__   ull    g_taps[2 * FILTER_L];   // staging: packed (k,k) pairs
__constant__ ull    c_kr2[FILTER_L];        // (kr,kr) pairs -> LDCU uniform path
__constant__ ull    c_ki2[FILTER_L];        // (ki,ki) pairs

// ---------------- helpers ----------------
__device__ __forceinline__ int swz(int i) { return i ^ ((i >> 4) & 0xF); }

__device__ __forceinline__ ull pack2(float lo, float hi) {
    ull v;
    asm("mov.b64 %0, {%1, %2};" : "=l"(v) : "f"(lo), "f"(hi));
    return v;
}

__device__ __forceinline__ void unpack2(ull v, float& lo, float& hi) {
    asm("mov.b64 {%0, %1}, %2;" : "=f"(lo), "=f"(hi) : "l"(v));
}

__device__ __forceinline__ ull fma2(ull a, ull b, ull c) {
    ull d;
    asm("fma.rn.f32x2 %0, %1, %2, %3;" : "=l"(d) : "l"(a), "l"(b), "l"(c));
    return d;
}

__device__ __forceinline__ float fast_sqrt(float x) {
    float r;
    asm("sqrt.approx.f32 %0, %1;" : "=f"(r) : "f"(x));
    return r;
}

// ------- LUT build + tap packing -------
// g(m) = OUT_SCALE * (sum_o w2[o]*tanh(w1[o]*m)) / m
__global__ void build_lut_kernel(const float* __restrict__ w1,
                                 const float* __restrict__ w2,
                                 const float* __restrict__ kr,
                                 const float* __restrict__ ki) {
    int i = blockIdx.x * blockDim.x + threadIdx.x;

    if (i < 2 * FILTER_L) {     // pack taps into staging buffer
        if (i < FILTER_L) {
            float a = kr[i];
            g_taps[i] = pack2(a, a);
        } else {
            float b = ki[i - FILTER_L];
            g_taps[i] = pack2(b, b);
        }
    }
    if (i >= LUT_N) return;

    float a[8], b[8];
#pragma unroll
    for (int o = 0; o < 8; o++) { a[o] = w1[o]; b[o] = w2[o]; }

    auto gf = [&](float m) -> float {
        if (m <= 0.0f) {
            float s = 0.0f;
#pragma unroll
            for (int o = 0; o < 8; o++) s += b[o] * a[o];   // lim h(m)/m
            return s;
        }
        float s = 0.0f;
#pragma unroll
        for (int o = 0; o < 8; o++) s += b[o] * tanhf(a[o] * m);
        return s / m;
    };

    float m0 = (float)i * (1.0f / LUT_SCALE);
    float g0 = gf(m0);
    float g1 = gf(m0 + (1.0f / LUT_SCALE));
    d_lut[i] = make_float2(OUT_SCALE * g0, OUT_SCALE * (g1 - g0));
}

// ---------------- fused envelope-MLP + complex FIR ----------------
__global__ void __launch_bounds__(THREADS, 3)
fused_fir_kernel(const float* __restrict__ xr, const float* __restrict__ xi,
                 float* __restrict__ out) {
    __shared__ float2 sg[SG_N];           // swizzled (gr, gi) pairs

    const int tid = threadIdx.x;
    const int row = blockIdx.y;
    const int w0  = blockIdx.x * TILE;

    const float* __restrict__ xrp = xr + (size_t)row * WIDTH + w0;
    const float* __restrict__ xip = xi + (size_t)row * WIDTH + w0;
    const int L = min(TILE + FILTER_L - 1, WIDTH - w0);  // valid inputs this tile

    // preprocess: float4 loads, mag -> LUT -> g, store (g*xr, g*xi) swizzled
    for (int g4 = tid; g4 < NGROUPS; g4 += THREADS) {
        const int idx = g4 * 4;
        float ar[4], ai[4];
        if (idx + 3 < L) {
            float4 vr = *reinterpret_cast<const float4*>(xrp + idx);
            float4 vi = *reinterpret_cast<const float4*>(xip + idx);
            ar[0] = vr.x; ar[1] = vr.y; ar[2] = vr.z; ar[3] = vr.w;
            ai[0] = vi.x; ai[1] = vi.y; ai[2] = vi.z; ai[3] = vi.w;
        } else {
#pragma unroll
            for (int k = 0; k < 4; k++) {
                ar[k] = (idx + k < L) ? __ldg(xrp + idx + k) : 0.0f;
                ai[k] = (idx + k < L) ? __ldg(xip + idx + k) : 0.0f;
            }
        }
#pragma unroll
        for (int k = 0; k < 4; k++) {
            float a = ar[k], b = ai[k];
            float s = fmaf(a, a, b * b);
            float m = fast_sqrt(s);
            float fi = fminf(m * LUT_SCALE, 4095.0f);
            int   ii = (int)fi;
            float fr = fi - (float)ii;
            float2 e = __ldg(&d_lut[ii]);
            float g = fmaf(e.y, fr, e.x);
            sg[swz(idx + k)] = make_float2(g * a, g * b);
        }
    }
    __syncthreads();

    // FIR: each thread produces RPT consecutive outputs with f32x2 FMAs.
    // Taps come from __constant__ (uniform-register path, zero LSU traffic).
    const int base = tid * RPT;

    ull acca[RPT], accb[RPT], Wn[RPT];
#pragma unroll
    for (int r = 0; r < RPT; r++) { acca[r] = 0ull; accb[r] = 0ull; }
#pragma unroll
    for (int r = 0; r < RPT; r++)
        Wn[r] = *reinterpret_cast<const ull*>(&sg[swz(base + r)]);

#pragma unroll
    for (int t = 0; t < FILTER_L; t++) {
        const ull k2 = c_kr2[t];
        const ull q2 = c_ki2[t];
#pragma unroll
        for (int r = 0; r < RPT; r++) {
            ull v = Wn[(t + r) & (RPT - 1)];
            acca[r] = fma2(v, k2, acca[r]);   // (sum kr*gr, sum kr*gi)
            accb[r] = fma2(v, q2, accb[r]);   // (sum ki*gr, sum ki*gi)
        }
        if (t < FILTER_L - 1)
            Wn[t & (RPT - 1)] =
                *reinterpret_cast<const ull*>(&sg[swz(base + t + RPT)]);
    }

    // epilogue: combine + store (vectorized STG.128 when 16B-aligned)
    const size_t oelem = (size_t)row * WOUT + w0 + base;   // float2 index
    float2* op = reinterpret_cast<float2*>(out) + oelem;
    const int rem = WOUT - (w0 + base);   // may be <= 0 for tail threads

    float y[RPT][2];
#pragma unroll
    for (int r = 0; r < RPT; r++) {
        float ax, ay, bx, by;
        unpack2(acca[r], ax, ay);
        unpack2(accb[r], bx, by);
        y[r][0] = ax - by;
        y[r][1] = ay + bx;
    }

    if (rem >= RPT && ((oelem & 1) == 0)) {
        float4* op4 = reinterpret_cast<float4*>(op);
        op4[0] = make_float4(y[0][0], y[0][1], y[1][0], y[1][1]);
        op4[1] = make_float4(y[2][0], y[2][1], y[3][0], y[3][1]);
    } else {
#pragma unroll
        for (int r = 0; r < RPT; r++)
            if (r < rem) op[r] = make_float2(y[r][0], y[r][1]);
    }
}

extern "C" void kernel_launch(void* const* d_in, const int* in_sizes, int n_in,
                              void* d_out, int out_size) {
    const float* xr = (const float*)d_in[0];   // x_real  [16,64,16384,1]
    const float* xi = (const float*)d_in[1];   // x_imag
    const float* w1 = (const float*)d_in[2];   // w_nl1 [8]
    const float* w2 = (const float*)d_in[3];   // w_nl2 [8]
    const float* kr = (const float*)d_in[4];   // w_lin_real [32]
    const float* ki = (const float*)d_in[5];   // w_lin_imag [32]
    float* out = (float*)d_out;

    build_lut_kernel<<<(LUT_N + 255) / 256, 256>>>(w1, w2, kr, ki);

    // publish packed taps to __constant__ (capturable D2D memcpy nodes)
    void* taps_addr = nullptr;
    cudaGetSymbolAddress(&taps_addr, g_taps);
    cudaMemcpyToSymbolAsync(c_kr2, taps_addr, FILTER_L * sizeof(ull), 0,
                            cudaMemcpyDeviceToDevice, 0);
    cudaMemcpyToSymbolAsync(c_ki2, (const char*)taps_addr + FILTER_L * sizeof(ull),
                            FILTER_L * sizeof(ull), 0,
                            cudaMemcpyDeviceToDevice, 0);

    dim3 grid((WOUT + TILE - 1) / TILE, NROWS);   // (8, 1024)
    fused_fir_kernel<<<grid, THREADS>>>(xr, xi, out);
}

// round 8
// speedup vs baseline: 1.4985x; 1.4985x over previous
#include <cuda_runtime.h>

typedef unsigned long long ull;

#define WIDTH     16384
#define WOUT      16353      // WIDTH - 32 + 1
#define NROWS     1024       // B*H = 16*64
#define FILTER_L  32
#define LUT_N     4096
#define LUT_SCALE 256.0f     // entries per unit of |x|; covers mag in [0,16)
#define TILE      1024
#define THREADS   128
#define RPT       8          // outputs per thread (TILE/THREADS)
#define SG_N      1056       // TILE + 31 halo, rounded to multiple of 16
#define NGROUPS   (SG_N/4)   // 264 float4-groups
#define OUT_SCALE 0.17782794100389226f  // sqrt(10^(-15/10))

__device__ float2 d_lut[LUT_N];

// ---------------- helpers ----------------
__device__ __forceinline__ int swz(int i) { return i ^ ((i >> 4) & 0xF); }

__device__ __forceinline__ ull pack2(float lo, float hi) {
    ull v;
    asm("mov.b64 %0, {%1, %2};" : "=l"(v) : "f"(lo), "f"(hi));
    return v;
}

__device__ __forceinline__ void unpack2(ull v, float& lo, float& hi) {
    asm("mov.b64 {%0, %1}, %2;" : "=f"(lo), "=f"(hi) : "l"(v));
}

__device__ __forceinline__ ull fma2(ull a, ull b, ull c) {
    ull d;
    asm("fma.rn.f32x2 %0, %1, %2, %3;" : "=l"(d) : "l"(a), "l"(b), "l"(c));
    return d;
}

__device__ __forceinline__ float fast_sqrt(float x) {
    float r;
    asm("sqrt.approx.f32 %0, %1;" : "=f"(r) : "f"(x));
    return r;
}

// ---------------- LUT build: g(m) = OUT_SCALE * (sum_o w2[o]*tanh(w1[o]*m)) / m ----------------
__global__ void build_lut_kernel(const float* __restrict__ w1,
                                 const float* __restrict__ w2) {
    int i = blockIdx.x * blockDim.x + threadIdx.x;
    if (i >= LUT_N) return;

    float a[8], b[8];
#pragma unroll
    for (int o = 0; o < 8; o++) { a[o] = w1[o]; b[o] = w2[o]; }

    auto gf = [&](float m) -> float {
        if (m <= 0.0f) {
            float s = 0.0f;
#pragma unroll
            for (int o = 0; o < 8; o++) s += b[o] * a[o];   // lim h(m)/m
            return s;
        }
        float s = 0.0f;
#pragma unroll
        for (int o = 0; o < 8; o++) s += b[o] * tanhf(a[o] * m);
        return s / m;
    };

    float m0 = (float)i * (1.0f / LUT_SCALE);
    float g0 = gf(m0);
    float g1 = gf(m0 + (1.0f / LUT_SCALE));
    d_lut[i] = make_float2(OUT_SCALE * g0, OUT_SCALE * (g1 - g0));
}

// ---------------- fused envelope-MLP + complex FIR ----------------
__global__ void __launch_bounds__(THREADS, 7)
fused_fir_kernel(const float* __restrict__ xr, const float* __restrict__ xi,
                 const float* __restrict__ kr, const float* __restrict__ ki,
                 float* __restrict__ out) {
    __shared__ float2 sg[SG_N];            // swizzled (gr, gi) pairs
    __shared__ ull    skq[FILTER_L * 2];   // per tap: [(kr,kr),(ki,ki)] 16B entry

    const int tid = threadIdx.x;
    const int row = blockIdx.y;
    const int w0  = blockIdx.x * TILE;

    if (tid < FILTER_L) {
        float a = kr[tid];
        float b = ki[tid];
        skq[2 * tid]     = pack2(a, a);
        skq[2 * tid + 1] = pack2(b, b);
    }

    const float* __restrict__ xrp = xr + (size_t)row * WIDTH + w0;
    const float* __restrict__ xip = xi + (size_t)row * WIDTH + w0;
    const int L = min(TILE + FILTER_L - 1, WIDTH - w0);  // valid inputs this tile

    // preprocess: float4 loads, mag -> LUT -> g, store (g*xr, g*xi) swizzled
    for (int g4 = tid; g4 < NGROUPS; g4 += THREADS) {
        const int idx = g4 * 4;
        float ar[4], ai[4];
        if (idx + 3 < L) {
            float4 vr = *reinterpret_cast<const float4*>(xrp + idx);
            float4 vi = *reinterpret_cast<const float4*>(xip + idx);
            ar[0] = vr.x; ar[1] = vr.y; ar[2] = vr.z; ar[3] = vr.w;
            ai[0] = vi.x; ai[1] = vi.y; ai[2] = vi.z; ai[3] = vi.w;
        } else {
#pragma unroll
            for (int k = 0; k < 4; k++) {
                ar[k] = (idx + k < L) ? __ldg(xrp + idx + k) : 0.0f;
                ai[k] = (idx + k < L) ? __ldg(xip + idx + k) : 0.0f;
            }
        }
#pragma unroll
        for (int k = 0; k < 4; k++) {
            float a = ar[k], b = ai[k];
            float s = fmaf(a, a, b * b);
            float m = fast_sqrt(s);
            float fi = fminf(m * LUT_SCALE, 4095.0f);
            int   ii = (int)fi;
            float fr = fi - (float)ii;
            float2 e = __ldg(&d_lut[ii]);
            float g = fmaf(e.y, fr, e.x);
            sg[swz(idx + k)] = make_float2(g * a, g * b);
        }
    }
    __syncthreads();

    // FIR: each thread produces RPT=8 consecutive outputs with f32x2 FMAs.
    // Per t: one LDS.128 tap broadcast + one LDS.64 window advance + 16 FFMA2.
    const int base = tid * RPT;

    ull acca[RPT], accb[RPT], Wn[RPT];
#pragma unroll
    for (int r = 0; r < RPT; r++) { acca[r] = 0ull; accb[r] = 0ull; }
#pragma unroll
    for (int r = 0; r < RPT; r++)
        Wn[r] = *reinterpret_cast<const ull*>(&sg[swz(base + r)]);

#pragma unroll
    for (int t = 0; t < FILTER_L; t++) {
        ull k2, q2;
        {
            ulonglong2 kk = *reinterpret_cast<const ulonglong2*>(&skq[2 * t]);
            k2 = kk.x;
            q2 = kk.y;
        }
#pragma unroll
        for (int r = 0; r < RPT; r++) {
            ull v = Wn[(t + r) & (RPT - 1)];
            acca[r] = fma2(v, k2, acca[r]);   // (sum kr*gr, sum kr*gi)
            accb[r] = fma2(v, q2, accb[r]);   // (sum ki*gr, sum ki*gi)
        }
        if (t < FILTER_L - 1)
            Wn[t & (RPT - 1)] =
                *reinterpret_cast<const ull*>(&sg[swz(base + t + RPT)]);
    }

    // epilogue: combine + store (STG.128 pairs when 16B-aligned)
    const size_t oelem = (size_t)row * WOUT + w0 + base;   // float2 index
    float2* op = reinterpret_cast<float2*>(out) + oelem;
    const int rem = WOUT - (w0 + base);   // may be <= 0 for tail threads

    float y[RPT][2];
#pragma unroll
    for (int r = 0; r < RPT; r++) {
        float ax, ay, bx, by;
        unpack2(acca[r], ax, ay);
        unpack2(accb[r], bx, by);
        y[r][0] = ax - by;
        y[r][1] = ay + bx;
    }

    if (rem >= RPT && ((oelem & 1) == 0)) {
        float4* op4 = reinterpret_cast<float4*>(op);
#pragma unroll
        for (int r = 0; r < RPT / 2; r++)
            op4[r] = make_float4(y[2 * r][0], y[2 * r][1],
                                 y[2 * r + 1][0], y[2 * r + 1][1]);
    } else {
#pragma unroll
        for (int r = 0; r < RPT; r++)
            if (r < rem) op[r] = make_float2(y[r][0], y[r][1]);
    }
}

extern "C" void kernel_launch(void* const* d_in, const int* in_sizes, int n_in,
                              void* d_out, int out_size) {
    const float* xr = (const float*)d_in[0];   // x_real  [16,64,16384,1]
    const float* xi = (const float*)d_in[1];   // x_imag
    const float* w1 = (const float*)d_in[2];   // w_nl1 [8]
    const float* w2 = (const float*)d_in[3];   // w_nl2 [8]
    const float* kr = (const float*)d_in[4];   // w_lin_real [32]
    const float* ki = (const float*)d_in[5];   // w_lin_imag [32]
    float* out = (float*)d_out;

    build_lut_kernel<<<(LUT_N + 255) / 256, 256>>>(w1, w2);

    dim3 grid((WOUT + TILE - 1) / TILE, NROWS);   // (16, 1024)
    fused_fir_kernel<<<grid, THREADS>>>(xr, xi, kr, ki, out);
}

// round 9
// speedup vs baseline: 1.5366x; 1.0255x over previous
#include <cuda_runtime.h>

typedef unsigned long long ull;

#define WIDTH     16384
#define WOUT      16353      // WIDTH - 32 + 1
#define NROWS     1024       // B*H = 16*64
#define FILTER_L  32
#define LUT_N     4096
#define LUT_SCALE 256.0f     // entries per unit of |x|; covers mag in [0,16)
#define TILE      1024
#define THREADS   128
#define RPT       8          // outputs per thread (TILE/THREADS)
#define SG_N      1056       // TILE + 31 halo, rounded to multiple of 16
#define NGROUPS   (SG_N/4)   // 264 float4-groups
#define OUT_SCALE 0.17782794100389226f  // sqrt(10^(-15/10))

__device__ float2 d_lut[LUT_N];

// ---------------- helpers ----------------
__device__ __forceinline__ int swz(int i) { return i ^ ((i >> 4) & 0xF); }

__device__ __forceinline__ ull pack2(float lo, float hi) {
    ull v;
    asm("mov.b64 %0, {%1, %2};" : "=l"(v) : "f"(lo), "f"(hi));
    return v;
}

__device__ __forceinline__ void unpack2(ull v, float& lo, float& hi) {
    asm("mov.b64 {%0, %1}, %2;" : "=f"(lo), "=f"(hi) : "l"(v));
}

__device__ __forceinline__ ull fma2(ull a, ull b, ull c) {
    ull d;
    asm("fma.rn.f32x2 %0, %1, %2, %3;" : "=l"(d) : "l"(a), "l"(b), "l"(c));
    return d;
}

__device__ __forceinline__ float fast_sqrt(float x) {
    float r;
    asm("sqrt.approx.f32 %0, %1;" : "=f"(r) : "f"(x));
    return r;
}

// ---------------- LUT build: g(m) = OUT_SCALE * (sum_o w2[o]*tanh(w1[o]*m)) / m ----------------
__global__ void build_lut_kernel(const float* __restrict__ w1,
                                 const float* __restrict__ w2) {
    int i = blockIdx.x * blockDim.x + threadIdx.x;
    if (i >= LUT_N) return;

    float a[8], b[8];
#pragma unroll
    for (int o = 0; o < 8; o++) { a[o] = w1[o]; b[o] = w2[o]; }

    auto gf = [&](float m) -> float {
        if (m <= 0.0f) {
            float s = 0.0f;
#pragma unroll
            for (int o = 0; o < 8; o++) s += b[o] * a[o];   // lim h(m)/m
            return s;
        }
        float s = 0.0f;
#pragma unroll
        for (int o = 0; o < 8; o++) s += b[o] * tanhf(a[o] * m);
        return s / m;
    };

    float m0 = (float)i * (1.0f / LUT_SCALE);
    float g0 = gf(m0);
    float g1 = gf(m0 + (1.0f / LUT_SCALE));
    d_lut[i] = make_float2(OUT_SCALE * g0, OUT_SCALE * (g1 - g0));
}

// ---------------- fused envelope-MLP + complex FIR ----------------
__global__ void __launch_bounds__(THREADS, 8)
fused_fir_kernel(const float* __restrict__ xr, const float* __restrict__ xi,
                 const float* __restrict__ kr, const float* __restrict__ ki,
                 float* __restrict__ out) {
    __shared__ float2 sg[SG_N];            // swizzled (gr, gi) pairs
    __shared__ ull    skq[FILTER_L * 2];   // per tap: [(kr,kr),(ki,ki)] 16B entry

    const int tid = threadIdx.x;
    const int row = blockIdx.y;
    const int w0  = blockIdx.x * TILE;

    if (tid < FILTER_L) {
        float a = kr[tid];
        float b = ki[tid];
        skq[2 * tid]     = pack2(a, a);
        skq[2 * tid + 1] = pack2(b, b);
    }

    const float* __restrict__ xrp = xr + (size_t)row * WIDTH + w0;
    const float* __restrict__ xip = xi + (size_t)row * WIDTH + w0;
    const int L = min(TILE + FILTER_L - 1, WIDTH - w0);  // valid inputs this tile

    // preprocess: float4 loads, mag -> LUT -> g, store (g*xr, g*xi) swizzled
    for (int g4 = tid; g4 < NGROUPS; g4 += THREADS) {
        const int idx = g4 * 4;
        float ar[4], ai[4];
        if (idx + 3 < L) {
            float4 vr = *reinterpret_cast<const float4*>(xrp + idx);
            float4 vi = *reinterpret_cast<const float4*>(xip + idx);
            ar[0] = vr.x; ar[1] = vr.y; ar[2] = vr.z; ar[3] = vr.w;
            ai[0] = vi.x; ai[1] = vi.y; ai[2] = vi.z; ai[3] = vi.w;
        } else {
#pragma unroll
            for (int k = 0; k < 4; k++) {
                ar[k] = (idx + k < L) ? __ldg(xrp + idx + k) : 0.0f;
                ai[k] = (idx + k < L) ? __ldg(xip + idx + k) : 0.0f;
            }
        }
#pragma unroll
        for (int k = 0; k < 4; k++) {
            float a = ar[k], b = ai[k];
            float s = fmaf(a, a, b * b);
            float m = fast_sqrt(s);
            float fi = fminf(m * LUT_SCALE, 4095.0f);
            int   ii = (int)fi;
            float fr = fi - (float)ii;
            float2 e = __ldg(&d_lut[ii]);
            float g = fmaf(e.y, fr, e.x);
            sg[swz(idx + k)] = make_float2(g * a, g * b);
        }
    }
    __syncthreads();

    // FIR: each thread produces RPT=8 consecutive outputs with f32x2 FMAs.
    // Tap pairs are double-buffered: tap t+1's LDS.128 issues before the
    // 16-FFMA2 burst of tap t, hiding the 29-cycle LDS latency.
    const int base = tid * RPT;

    ull acca[RPT], accb[RPT], Wn[RPT];
#pragma unroll
    for (int r = 0; r < RPT; r++) { acca[r] = 0ull; accb[r] = 0ull; }
#pragma unroll
    for (int r = 0; r < RPT; r++)
        Wn[r] = *reinterpret_cast<const ull*>(&sg[swz(base + r)]);

    ulonglong2 kk = *reinterpret_cast<const ulonglong2*>(&skq[0]);

#pragma unroll
    for (int t = 0; t < FILTER_L; t++) {
        ulonglong2 kk_next;
        if (t < FILTER_L - 1)
            kk_next = *reinterpret_cast<const ulonglong2*>(&skq[2 * (t + 1)]);
        const ull k2 = kk.x;
        const ull q2 = kk.y;
#pragma unroll
        for (int r = 0; r < RPT; r++) {
            ull v = Wn[(t + r) & (RPT - 1)];
            acca[r] = fma2(v, k2, acca[r]);   // (sum kr*gr, sum kr*gi)
            accb[r] = fma2(v, q2, accb[r]);   // (sum ki*gr, sum ki*gi)
        }
        if (t < FILTER_L - 1) {
            Wn[t & (RPT - 1)] =
                *reinterpret_cast<const ull*>(&sg[swz(base + t + RPT)]);
            kk = kk_next;
        }
    }

    // epilogue: combine + store (STG.128 pairs when 16B-aligned)
    const size_t oelem = (size_t)row * WOUT + w0 + base;   // float2 index
    float2* op = reinterpret_cast<float2*>(out) + oelem;
    const int rem = WOUT - (w0 + base);   // may be <= 0 for tail threads

    float y[RPT][2];
#pragma unroll
    for (int r = 0; r < RPT; r++) {
        float ax, ay, bx, by;
        unpack2(acca[r], ax, ay);
        unpack2(accb[r], bx, by);
        y[r][0] = ax - by;
        y[r][1] = ay + bx;
    }

    if (rem >= RPT && ((oelem & 1) == 0)) {
        float4* op4 = reinterpret_cast<float4*>(op);
#pragma unroll
        for (int r = 0; r < RPT / 2; r++)
            op4[r] = make_float4(y[2 * r][0], y[2 * r][1],
                                 y[2 * r + 1][0], y[2 * r + 1][1]);
    } else {
#pragma unroll
        for (int r = 0; r < RPT; r++)
            if (r < rem) op[r] = make_float2(y[r][0], y[r][1]);
    }
}

extern "C" void kernel_launch(void* const* d_in, const int* in_sizes, int n_in,
                              void* d_out, int out_size) {
    const float* xr = (const float*)d_in[0];   // x_real  [16,64,16384,1]
    const float* xi = (const float*)d_in[1];   // x_imag
    const float* w1 = (const float*)d_in[2];   // w_nl1 [8]
    const float* w2 = (const float*)d_in[3];   // w_nl2 [8]
    const float* kr = (const float*)d_in[4];   // w_lin_real [32]
    const float* ki = (const float*)d_in[5];   // w_lin_imag [32]
    float* out = (float*)d_out;

    build_lut_kernel<<<(LUT_N + 255) / 256, 256>>>(w1, w2);

    dim3 grid((WOUT + TILE - 1) / TILE, NROWS);   // (16, 1024)
    fused_fir_kernel<<<grid, THREADS>>>(xr, xi, kr, ki, out);
}